// round 14
// baseline (speedup 1.0000x reference)
#include <cuda_runtime.h>
#include <cuda_bf16.h>
#include <math.h>
#include <stdint.h>

// Problem constants
#define NB 4
#define NS 8192
#define NHID 768
#define NH 12
#define ND 64
#define NK 16
#define NMB (NS/NK)          // 512
#define NTOK (NB*NS)         // 32768
#define KSP 2304             // split-K (3 x 768)
#define NCH 36               // K chunks of 64
#define NBH (NB*NH)          // 48

// ---------------- scratch (device globals; no allocs allowed) ----------------
__device__ __nv_bfloat16 g_asplit[(size_t)NTOK*KSP]; // split A (x, later G)
__device__ float g_qvg[(size_t)NTOK*KSP];            // fused q|v|gate output f32
__device__ __nv_bfloat16 g_bt1[(size_t)KSP*KSP];     // Bt for qvg gemm
__device__ __nv_bfloat16 g_bt2[(size_t)NHID*KSP];    // Bt for wo gemm
// per-(bh,mb) packed record, 12288 B = 768 uint4 (all swizzled bf16 16x128B):
//   [0,2048) qh | [2048,4096) ql | [4096,6144) kh | [6144,8192) kl
//   [8192,10240) vh | [10240,12288) vl
__device__ uint4 g_rec[(size_t)NBH*NMB*768];
__device__ float g_coef[(size_t)NBH*NMB*256];        // coef' per minibatch
__device__ float g_Z[(size_t)NTOK*NHID];             // scan output [B,S,H*D]
__device__ float g_eta[NB*NH*NS];
__device__ float g_invf[32];                         // rope inv_freq table

__device__ __forceinline__ float warpAllSum(float v) {
#pragma unroll
    for (int o = 16; o; o >>= 1) v += __shfl_xor_sync(0xffffffffu, v, o);
    return v;
}

__device__ __forceinline__ uint32_t smem_u32(const void* p) {
    uint32_t a;
    asm("{ .reg .u64 t; cvta.to.shared.u64 t, %1; cvt.u32.u64 %0, t; }"
        : "=r"(a) : "l"(p));
    return a;
}

#define CPA16(sa, gp) \
    asm volatile("cp.async.cg.shared.global [%0], [%1], 16;" \
        :: "r"(sa), "l"(__cvta_generic_to_global(gp)) : "memory")
#define CPA_COMMIT() asm volatile("cp.async.commit_group;" ::: "memory")
#define CPA_WAIT2()  asm volatile("cp.async.wait_group 2;" ::: "memory")
#define CPA_WAIT1()  asm volatile("cp.async.wait_group 1;" ::: "memory")
#define CPA_WAIT0()  asm volatile("cp.async.wait_group 0;" ::: "memory")

__device__ __forceinline__ void ldsm4(uint32_t* r, uint32_t a) {
    asm volatile("ldmatrix.sync.aligned.m8n8.x4.shared.b16 {%0,%1,%2,%3}, [%4];"
        : "=r"(r[0]), "=r"(r[1]), "=r"(r[2]), "=r"(r[3]) : "r"(a));
}
__device__ __forceinline__ void ldsm4t(uint32_t* r, uint32_t a) {
    asm volatile("ldmatrix.sync.aligned.m8n8.x4.trans.shared.b16 {%0,%1,%2,%3}, [%4];"
        : "=r"(r[0]), "=r"(r[1]), "=r"(r[2]), "=r"(r[3]) : "r"(a));
}
__device__ __forceinline__ void ldsm2t(uint32_t& r0, uint32_t& r1, uint32_t a) {
    asm volatile("ldmatrix.sync.aligned.m8n8.x2.trans.shared.b16 {%0,%1}, [%2];"
        : "=r"(r0), "=r"(r1) : "r"(a));
}
__device__ __forceinline__ void mma16816(float* c, const uint32_t* a,
                                         const uint32_t* b) {
    asm volatile("mma.sync.aligned.m16n8k16.row.col.f32.bf16.bf16.f32 "
        "{%0,%1,%2,%3}, {%4,%5,%6,%7}, {%8,%9}, {%0,%1,%2,%3};"
        : "+f"(c[0]), "+f"(c[1]), "+f"(c[2]), "+f"(c[3])
        : "r"(a[0]), "r"(a[1]), "r"(a[2]), "r"(a[3]), "r"(b[0]), "r"(b[1]));
}

__device__ __forceinline__ uint32_t pkhi(float a, float b) {
    __nv_bfloat16 x = __float2bfloat16(a), y = __float2bfloat16(b);
    uint16_t ux = *(uint16_t*)&x, uy = *(uint16_t*)&y;
    return (uint32_t)ux | ((uint32_t)uy << 16);
}
__device__ __forceinline__ float flo(float v) {
    return v - __bfloat162float(__float2bfloat16(v));
}
// swizzled byte offset of bf16 element (row, col) in a 16x128B tile
__device__ __forceinline__ uint32_t tile_off(int row, int col) {
    return (uint32_t)(row * 128 + ((((col >> 3) ^ row) & 7) << 4) +
                      ((2 * col) & 15));
}

// ======================= mma.sync GEMM: C = A * Bt^T ==========================
#define STAGE_BYTES 16384
__global__ __launch_bounds__(256) void mma_gemm(
    const __nv_bfloat16* __restrict__ A, const __nv_bfloat16* __restrict__ Bt,
    float* __restrict__ C, int ldc)
{
    extern __shared__ char dsm[];
    uint32_t sbase = (smem_u32(dsm) + 1023u) & ~1023u;
    uint32_t aS = sbase;
    uint32_t bS = sbase + 3 * STAGE_BYTES;

    int tid = threadIdx.x, lane = tid & 31, w = tid >> 5;
    int m0 = blockIdx.y * 128, n0 = blockIdx.x * 128;
    int mw = (w & 1) * 64, nw = (w >> 1) * 32;

    int r0 = tid >> 3, cg = tid & 7;
    uint32_t st_off = (uint32_t)(r0 * 128 + ((cg * 16) ^ ((r0 & 7) << 4)));
    const __nv_bfloat16* ga = A  + (size_t)(m0 + r0) * KSP + cg * 8;
    const __nv_bfloat16* gb = Bt + (size_t)(n0 + r0) * KSP + cg * 8;

#pragma unroll
    for (int j = 0; j < 3; j++) {
#pragma unroll
        for (int t = 0; t < 4; t++) {
            CPA16(aS + j * STAGE_BYTES + st_off + t * 4096,
                  ga + (size_t)t * 32 * KSP + j * 64);
            CPA16(bS + j * STAGE_BYTES + st_off + t * 4096,
                  gb + (size_t)t * 32 * KSP + j * 64);
        }
        CPA_COMMIT();
    }

    uint32_t swz = (uint32_t)((lane & 7) << 4);
    uint32_t a_row_byte = (uint32_t)((mw + (lane & 15)) * 128);
    uint32_t a_khalf = (uint32_t)((lane >> 4) * 16);
    uint32_t b_row_byte = (uint32_t)((nw + (lane & 7) + ((lane >> 4) << 3)) * 128);
    uint32_t b_khalf = (uint32_t)(((lane >> 3) & 1) * 16);

    float cacc[4][4][4];
#pragma unroll
    for (int i = 0; i < 4; i++)
#pragma unroll
        for (int j = 0; j < 4; j++)
#pragma unroll
            for (int k = 0; k < 4; k++) cacc[i][j][k] = 0.f;

    for (int i = 0; i < NCH; i++) {
        int si = i % 3;
        CPA_WAIT2();
        __syncthreads();
        uint32_t aT = aS + si * STAGE_BYTES;
        uint32_t bT = bS + si * STAGE_BYTES;
#pragma unroll
        for (int ks = 0; ks < 4; ks++) {
            uint32_t afr[4][4], bfr[4][2];
#pragma unroll
            for (int am = 0; am < 4; am++) {
                uint32_t row_b = a_row_byte + am * (16 * 128);
                ldsm4(afr[am], aT + row_b + ((ks * 32 + a_khalf) ^ swz));
            }
#pragma unroll
            for (int bg = 0; bg < 2; bg++) {
                uint32_t t4[4];
                uint32_t row_b = b_row_byte + bg * (16 * 128);
                ldsm4(t4, bT + row_b + ((ks * 32 + b_khalf) ^ swz));
                bfr[bg * 2 + 0][0] = t4[0]; bfr[bg * 2 + 0][1] = t4[1];
                bfr[bg * 2 + 1][0] = t4[2]; bfr[bg * 2 + 1][1] = t4[3];
            }
#pragma unroll
            for (int am = 0; am < 4; am++)
#pragma unroll
                for (int bn = 0; bn < 4; bn++)
                    mma16816(cacc[am][bn], afr[am], bfr[bn]);
        }
        __syncthreads();
        int jn = i + 3;
        if (jn < NCH) {
#pragma unroll
            for (int t = 0; t < 4; t++) {
                CPA16(aS + si * STAGE_BYTES + st_off + t * 4096,
                      ga + (size_t)t * 32 * KSP + jn * 64);
                CPA16(bS + si * STAGE_BYTES + st_off + t * 4096,
                      gb + (size_t)t * 32 * KSP + jn * 64);
            }
        }
        CPA_COMMIT();
    }

    int erow = lane >> 2, ecol = (lane & 3) * 2;
#pragma unroll
    for (int am = 0; am < 4; am++) {
#pragma unroll
        for (int bn = 0; bn < 4; bn++) {
            int r = m0 + mw + am * 16 + erow;
            int c = n0 + nw + bn * 8 + ecol;
            *(float2*)&C[(size_t)r * ldc + c] =
                make_float2(cacc[am][bn][0], cacc[am][bn][1]);
            *(float2*)&C[(size_t)(r + 8) * ldc + c] =
                make_float2(cacc[am][bn][2], cacc[am][bn][3]);
        }
    }
}

// ---------------- rope inv_freq table (double-rounded, once) ------------------
__global__ void rope_init_kernel()
{
    int p = threadIdx.x;
    double ex = (double)(2 * p) / 64.0;
    g_invf[p] = (float)exp(-ex * 9.210340371976184);   // 10000^-ex
}

// ---------------- conversion: x -> split bf16 [Ah|Al|Ah] ----------------------
__global__ __launch_bounds__(256) void split_x_kernel(const float* __restrict__ x)
{
    size_t t = blockIdx.x;
    __nv_bfloat16* dst = g_asplit + t * KSP;
    const float* src = x + t * NHID;
#pragma unroll
    for (int u = 0; u < 3; u++) {
        int cidx = threadIdx.x + (u << 8);
        float v = src[cidx];
        __nv_bfloat16 hi = __float2bfloat16(v);
        __nv_bfloat16 lo = __float2bfloat16(v - __bfloat162float(hi));
        dst[cidx] = hi;
        dst[NHID + cidx] = lo;
        dst[2 * NHID + cidx] = hi;
    }
}

// -------- build transposed split weights via smem transpose (coalesced) -------
__global__ __launch_bounds__(256) void build_bt_t_kernel(
    __nv_bfloat16* __restrict__ dst, const float* __restrict__ w, int np_base)
{
    __shared__ float t[32][33];
    int n0 = blockIdx.x * 32, k0 = blockIdx.y * 32;
    int tx = threadIdx.x & 31, ty = threadIdx.x >> 5;   // 32 x 8
#pragma unroll
    for (int i = ty; i < 32; i += 8)
        t[i][tx] = w[(size_t)(k0 + i) * NHID + n0 + tx];
    __syncthreads();
#pragma unroll
    for (int r = ty; r < 32; r += 8) {
        float v = t[tx][r];
        __nv_bfloat16 hi = __float2bfloat16(v);
        __nv_bfloat16 lo = __float2bfloat16(v - __bfloat162float(hi));
        __nv_bfloat16* drow = dst + (size_t)(np_base + n0 + r) * KSP + k0 + tx;
        drow[0] = hi;
        drow[NHID] = hi;
        drow[2 * NHID] = lo;
    }
}

// ---------------- ttt_lr_eta = sigmoid(x . lr_w[h] + lr_b[h]) / D -------------
__global__ __launch_bounds__(256) void lr_kernel(
    const float* __restrict__ x, const float* __restrict__ lrw,
    const float* __restrict__ lrb)
{
    int gw = (blockIdx.x * blockDim.x + threadIdx.x) >> 5;
    int lane = threadIdx.x & 31;
    const float* xr = x + (size_t)gw * NHID;
    float xv[24];
#pragma unroll
    for (int u = 0; u < 24; u++) xv[u] = xr[lane + (u << 5)];
    int b = gw >> 13;
    int s = gw & (NS - 1);
    for (int h = 0; h < NH; h++) {
        const float* wr = lrw + h * NHID;
        float sum = 0.f;
#pragma unroll
        for (int u = 0; u < 24; u++) sum += xv[u] * wr[lane + (u << 5)];
        sum = warpAllSum(sum);
        if (lane == 0) {
            float zv = sum + lrb[h];
            g_eta[((size_t)b * NH + h) * NS + s] =
                (1.0f / (1.0f + expf(-zv))) * (1.0f / (float)ND);
        }
    }
}

// ------ causal dwconv + RoPE -> slim record (bf16 hi/lo tiles) + coef' --------
__global__ __launch_bounds__(512) void conv_rope_kernel(
    const float* __restrict__ cqw, const float* __restrict__ cqb,
    const float* __restrict__ ckw, const float* __restrict__ ckb,
    const float* __restrict__ lti)
{
    __shared__ float qs[16 * 68], ks[16 * 68], tkl[16];
    int mb = blockIdx.x, bh = blockIdx.y;
    int b = bh / NH, h = bh % NH;
    int tid = threadIdx.x;
    int w = tid >> 5, p = tid & 31;
    int s = mb * NK + w;
    int c0 = h * ND + 2 * p;

    float qe = cqb[c0], qo = cqb[c0 + 1];
    float ke = ckb[c0], ko = ckb[c0 + 1];
    const float* xb = g_qvg + ((size_t)b * NS) * KSP + c0;
#pragma unroll
    for (int kk = 0; kk < 4; kk++) {
        int ss = s + kk - 4;
        if (ss >= 0) {
            float2 xv2 = *(const float2*)(xb + (size_t)ss * KSP);
            float2 w1 = *(const float2*)(cqw + kk * NHID + c0);
            float2 w2 = *(const float2*)(ckw + kk * NHID + c0);
            qe += w1.x * xv2.x; qo += w1.y * xv2.y;
            ke += w2.x * xv2.x; ko += w2.y * xv2.y;
        }
    }
    float invf = g_invf[p];
    float ang = (float)s * invf;
    float sn, cn;
    sincosf(ang, &sn, &cn);

    float2 qO = make_float2(qe * cn - qo * sn, qe * sn + qo * cn);
    float2 kO = make_float2(ke * cn - ko * sn, ke * sn + ko * cn);
    float2 vv = *(const float2*)(g_qvg + ((size_t)b * NS + s) * KSP + NHID + c0);

    char* rec = (char*)g_rec + ((size_t)bh * NMB + mb) * 12288;
    uint32_t so = (uint32_t)(w * 128 + ((((p >> 2) ^ w) & 7) << 4) + 4 * (p & 3));

    *(uint32_t*)(rec + 0     + so) = pkhi(qO.x, qO.y);
    *(uint32_t*)(rec + 2048  + so) = pkhi(flo(qO.x), flo(qO.y));
    *(uint32_t*)(rec + 4096  + so) = pkhi(kO.x, kO.y);
    *(uint32_t*)(rec + 6144  + so) = pkhi(flo(kO.x), flo(kO.y));
    *(uint32_t*)(rec + 8192  + so) = pkhi(vv.x, vv.y);
    *(uint32_t*)(rec + 10240 + so) = pkhi(flo(vv.x), flo(vv.y));

    qs[w * 68 + 2 * p] = qO.x; qs[w * 68 + 2 * p + 1] = qO.y;
    ks[w * 68 + 2 * p] = kO.x; ks[w * 68 + 2 * p + 1] = kO.y;
    if (tid < 16) tkl[tid] = fmaxf(1.0f / (float)(tid + 1) + lti[tid], 0.0f);
    __syncthreads();

    if (tid < 256) {
        int i = tid >> 4, j = tid & 15;
        float a = 0.f;
#pragma unroll 8
        for (int d = 0; d < ND; d++) a += qs[i * 68 + d] * ks[j * 68 + d];
        float invlc = 1.0f / tkl[15];
        g_coef[((size_t)bh * NMB + mb) * 256 + tid] =
            (j <= i) ? tkl[i] * (a + 1.0f) * invlc : 0.0f;
    }
}

// ---------------- pipelined TTT scan: 48 blocks, 512 threads ------------------
// smem float offsets
#define FW1M  0          // 64*72
#define FZB   4608       // 2 parities x (zk 1152 | zq 1152)
#define FSG   9216       // 16*72
#define FB1   10368
#define FGSC  10432
#define FGBI  10496
#define FETA  10560      // 4*16
#define FCOEF 10624      // 4*256
#define FLC   11648
// byte offsets
#define BW1H  46720
#define BW1L  54912
#define BSGH  63104
#define BSGL  65152
#define BBUF  67200      // 4 x 12288 ring
#define SCAN_DSM 116352

#define FZK(par) (FZB + (par) * 2304)
#define FZQ(par) (FZB + (par) * 2304 + 1152)

// Z/preZ-style: acc += kq(tiles at Ab) @ W1(tiles at sb+BW1H/L), warp (n8)
__device__ __forceinline__ void kqW1_mma(uint32_t Ab, uint32_t sb, int rr,
                                         int hf, int n8, float* acc)
{
    uint32_t ah[4][4], al[4][4];
#pragma unroll
    for (int c = 0; c < 4; c++) {
        uint32_t ad = Ab + rr * 128 + ((((c << 1) | hf) ^ (rr & 7)) << 4);
        ldsm4(ah[c], ad);
        ldsm4(al[c], ad + 2048);
    }
    uint32_t bhf[4][2], blf[4][2];
#pragma unroll
    for (int c = 0; c < 4; c++) {
        int rb = (c << 4) + rr;
        uint32_t woff = (uint32_t)(rb * 128 + ((n8 ^ (rb & 7)) << 4));
        ldsm2t(bhf[c][0], bhf[c][1], sb + BW1H + woff);
        ldsm2t(blf[c][0], blf[c][1], sb + BW1L + woff);
    }
#pragma unroll
    for (int c = 0; c < 4; c++) mma16816(acc, ah[c], bhf[c]);
#pragma unroll
    for (int c = 0; c < 4; c++) mma16816(acc, al[c], bhf[c]);
#pragma unroll
    for (int c = 0; c < 4; c++) mma16816(acc, ah[c], blf[c]);
}

// X = kq(As tiles, 16x64) @ k(Bs tiles, 16x64)^T -> negated bf16 A-frags
__device__ __forceinline__ void x_mma(uint32_t As, uint32_t Bs, int rr, int hf,
                                      int lane, uint32_t* axh, uint32_t* axl)
{
    float cX0[4] = {0, 0, 0, 0}, cX1[4] = {0, 0, 0, 0};
    uint32_t brow = (uint32_t)((lane & 7) + ((lane >> 4) << 3));
    uint32_t bhalf = (uint32_t)((lane >> 3) & 1);
#pragma unroll
    for (int c = 0; c < 4; c++) {
        uint32_t ad = As + rr * 128 + ((((c << 1) | hf) ^ (rr & 7)) << 4);
        uint32_t a_h[4], a_l[4];
        ldsm4(a_h, ad);
        ldsm4(a_l, ad + 2048);
        uint32_t bg = (uint32_t)(2 * c) + bhalf;
        uint32_t ba = Bs + brow * 128 + ((bg ^ (brow & 7)) << 4);
        uint32_t tb[4];
        ldsm4(tb, ba);
        uint32_t b0h[2] = {tb[0], tb[1]}, b1h[2] = {tb[2], tb[3]};
        ldsm4(tb, ba + 2048);
        uint32_t b0l[2] = {tb[0], tb[1]}, b1l[2] = {tb[2], tb[3]};
        mma16816(cX0, a_h, b0h); mma16816(cX0, a_l, b0h); mma16816(cX0, a_h, b0l);
        mma16816(cX1, a_h, b1h); mma16816(cX1, a_l, b1h); mma16816(cX1, a_h, b1l);
    }
    float v0 = -cX0[0], v1 = -cX0[1], v2 = -cX0[2], v3 = -cX0[3];
    float u0 = -cX1[0], u1 = -cX1[1], u2 = -cX1[2], u3 = -cX1[3];
    axh[0] = pkhi(v0, v1); axh[1] = pkhi(v2, v3);
    axh[2] = pkhi(u0, u1); axh[3] = pkhi(u2, u3);
    axl[0] = pkhi(flo(v0), flo(v1)); axl[1] = pkhi(flo(v2), flo(v3));
    axl[2] = pkhi(flo(u0), flo(u1)); axl[3] = pkhi(flo(u2), flo(u3));
}

__global__ __launch_bounds__(512) void scan_kernel(
    const float* __restrict__ lti, const float* __restrict__ tns,
    const float* __restrict__ tnb, const float* __restrict__ W1g,
    const float* __restrict__ b1g)
{
    extern __shared__ char SMC[];
    float* S = (float*)SMC;
    uint32_t sb = smem_u32(SMC);

    int bh = blockIdx.x;
    int b = bh / NH, h = bh % NH;
    int tid = threadIdx.x;
    int w = tid >> 5, lane = tid & 31;
    int mt = w & 1, n8 = w >> 1;
    int rr = lane & 15, hf = lane >> 4;

    for (int i = tid; i < ND * ND; i += 512) {
        int d = i >> 6, e = i & 63;
        float wv = W1g[h * ND * ND + i];
        S[FW1M + d * 72 + e] = wv;
        uint32_t off = tile_off(d, e);
        *(__nv_bfloat16*)(SMC + BW1H + off) = __float2bfloat16(wv);
        *(__nv_bfloat16*)(SMC + BW1L + off) = __float2bfloat16(flo(wv));
    }
    if (tid < ND) {
        S[FB1 + tid]  = b1g[h * ND + tid];
        S[FGSC + tid] = tns[h * ND + tid];
        S[FGBI + tid] = tnb[h * ND + tid];
    }
    if (tid == 0) S[FLC] = fmaxf(1.0f / 16.0f + lti[15], 0.0f);

    const uint4* recb = g_rec + (size_t)bh * NMB * 768;
    const float* eg = g_eta + (size_t)bh * NS;
    const float* cfb = g_coef + (size_t)bh * NMB * 256;
    float* zg = g_Z + (size_t)b * NS * NHID + h * ND;

    // prefetch slots 0,1,2 in one group
    for (int sl = 0; sl < 3; sl++) {
        const uint4* rec = recb + (size_t)sl * 768;
        for (int idx = tid; idx < 836; idx += 512) {
            if (idx < 768) {
                CPA16(sb + BBUF + sl * 12288 + idx * 16, rec + idx);
            } else if (idx < 832) {
                int c = idx - 768;
                CPA16(sb + (FCOEF + sl * 256) * 4 + c * 16,
                      cfb + (size_t)sl * 256 + c * 4);
            } else {
                int c = idx - 832;
                CPA16(sb + (FETA + sl * 16) * 4 + c * 16,
                      eg + (size_t)sl * 16 + c * 4);
            }
        }
    }
    CPA_COMMIT();
    CPA_WAIT0();
    __syncthreads();

    uint32_t axh[4], axl[4];
    float preZ[4];

    // prologue: Z(0) = KQ(0)@W1init (no b1); X(0); preZ(1)
    {
        uint32_t A0 = sb + BBUF + (mt ? 0u : 4096u);
        float acc[4] = {0, 0, 0, 0};
        kqW1_mma(A0, sb, rr, hf, n8, acc);
        float* Z = S + (mt ? FZQ(0) : FZK(0));
        int e = n8 * 8 + (lane & 3) * 2, r0 = lane >> 2;
        *(float2*)&Z[r0 * 72 + e] = make_float2(acc[0], acc[1]);
        *(float2*)&Z[(r0 + 8) * 72 + e] = make_float2(acc[2], acc[3]);

        uint32_t A1 = sb + BBUF + 12288 + (mt ? 0u : 4096u);
        x_mma(A1, sb + BBUF + 4096, rr, hf, lane, axh, axl);
        preZ[0] = preZ[1] = preZ[2] = preZ[3] = 0.f;
        kqW1_mma(A1, sb, rr, hf, n8, preZ);
    }
    __syncthreads();

    for (int mb = 0; mb < NMB; mb++) {
        int sl = mb & 3;
        uint32_t bufB = (uint32_t)(BBUF + sl * 12288);

        // top: prefetch mb+3 into slot (mb+3)&3 (dead since last iteration)
        if (mb <= 508) {
            int tsl = (mb + 3) & 3;
            const uint4* rec = recb + (size_t)(mb + 3) * 768;
            for (int idx = tid; idx < 836; idx += 512) {
                if (idx < 768) {
                    CPA16(sb + BBUF + tsl * 12288 + idx * 16, rec + idx);
                } else if (idx < 832) {
                    int c = idx - 768;
                    CPA16(sb + (FCOEF + tsl * 256) * 4 + c * 16,
                          cfb + (size_t)(mb + 3) * 256 + c * 4);
                } else {
                    int c = idx - 832;
                    CPA16(sb + (FETA + tsl * 16) * 4 + c * 16,
                          eg + (size_t)(mb + 3) * 16 + c * 4);
                }
            }
        }
        CPA_COMMIT();

        // ---- P2 (row w): LN-L2 bwd on Zk(mb)+b1 -> SG ------------------------
        float b1o0, b1o1;
        {
            int c0 = lane, c1 = lane + 32;
            b1o0 = S[FB1 + c0]; b1o1 = S[FB1 + c1];
            float z0 = S[FZK(mb & 1) + w * 72 + c0] + b1o0;
            float z1 = S[FZK(mb & 1) + w * 72 + c1] + b1o1;
            float mu = warpAllSum(z0 + z1) * (1.f / 64.f);
            float var = warpAllSum(z0 * z0 + z1 * z1) * (1.f / 64.f) - mu * mu;
            float rstd = rsqrtf(var + 1e-5f);
            float xh0 = (z0 - mu) * rstd, xh1 = (z1 - mu) * rstd;
            float g0 = S[FGSC + c0], g1 = S[FGSC + c1];
            uint32_t to0 = tile_off(w, c0), to1 = tile_off(w, c1);
            float t0 =
                (__bfloat162float(*(__nv_bfloat16*)(SMC + bufB + 8192 + to0)) +
                 __bfloat162float(*(__nv_bfloat16*)(SMC + bufB + 10240 + to0))) -
                (__bfloat162float(*(__nv_bfloat16*)(SMC + bufB + 4096 + to0)) +
                 __bfloat162float(*(__nv_bfloat16*)(SMC + bufB + 6144 + to0)));
            float t1 =
                (__bfloat162float(*(__nv_bfloat16*)(SMC + bufB + 8192 + to1)) +
                 __bfloat162float(*(__nv_bfloat16*)(SMC + bufB + 10240 + to1))) -
                (__bfloat162float(*(__nv_bfloat16*)(SMC + bufB + 4096 + to1)) +
                 __bfloat162float(*(__nv_bfloat16*)(SMC + bufB + 6144 + to1)));
            float gx0 = (xh0 * g0 + S[FGBI + c0] - t0) * g0;
            float gx1 = (xh1 * g1 + S[FGBI + c1] - t1) * g1;
            float m1 = warpAllSum(gx0 + gx1) * (1.f / 64.f);
            float m2 = warpAllSum(gx0 * xh0 + gx1 * xh1) * (1.f / 64.f);
            float sgs = S[FLC] * S[FETA + sl * 16 + w];
            float sg0 = sgs * (gx0 - m1 - xh0 * m2) * rstd;
            float sg1 = sgs * (gx1 - m1 - xh1 * m2) * rstd;
            S[FSG + w * 72 + c0] = sg0;
            S[FSG + w * 72 + c1] = sg1;
            *(__nv_bfloat16*)(SMC + BSGH + to0) = __float2bfloat16(sg0);
            *(__nv_bfloat16*)(SMC + BSGH + to1) = __float2bfloat16(sg1);
            *(__nv_bfloat16*)(SMC + BSGL + to0) = __float2bfloat16(flo(sg0));
            *(__nv_bfloat16*)(SMC + BSGL + to1) = __float2bfloat16(flo(sg1));
        }
        __syncthreads();                                   // s1

        // ---- C: Z(mb+1) = preZ + (-X)@SG  (3 mma) ---------------------------
        if (mb <= 510) {
            uint32_t so = (uint32_t)(rr * 128 + ((n8 ^ (rr & 7)) << 4));
            uint32_t bsh[2], bsl[2];
            ldsm2t(bsh[0], bsh[1], sb + BSGH + so);
            ldsm2t(bsl[0], bsl[1], sb + BSGL + so);
            float acc[4] = {preZ[0], preZ[1], preZ[2], preZ[3]};
            mma16816(acc, axh, bsh);
            mma16816(acc, axl, bsh);
            mma16816(acc, axh, bsl);
            int par = (mb + 1) & 1;
            float* Z = S + (mt ? FZQ(par) : FZK(par));
            int e = n8 * 8 + (lane & 3) * 2, r0 = lane >> 2;
            *(float2*)&Z[r0 * 72 + e] = make_float2(acc[0], acc[1]);
            *(float2*)&Z[(r0 + 8) * 72 + e] = make_float2(acc[2], acc[3]);
        }
        // ---- A1: W1 -= k^T @ SG ; b1 -= sum SG ------------------------------
        {
            int dm = w & 3, np = w >> 2;
            uint32_t kb = sb + bufB + 4096;
            uint32_t adr = kb + rr * 128 + ((((dm << 1) | hf) ^ (rr & 7)) << 4);
            uint32_t tmp[4], akh[4], akl[4];
            ldsm4t(tmp, adr);
            akh[0] = tmp[0]; akh[1] = tmp[2]; akh[2] = tmp[1]; akh[3] = tmp[3];
            ldsm4t(tmp, adr + 2048);
            akl[0] = tmp[0]; akl[1] = tmp[2]; akl[2] = tmp[1]; akl[3] = tmp[3];
#pragma unroll
            for (int sdx = 0; sdx < 2; sdx++) {
                int nn8 = 2 * np + sdx;
                uint32_t so = (uint32_t)(rr * 128 + ((nn8 ^ (rr & 7)) << 4));
                uint32_t bsh[2], bsl[2];
                ldsm2t(bsh[0], bsh[1], sb + BSGH + so);
                ldsm2t(bsl[0], bsl[1], sb + BSGL + so);
                float d4[4] = {0, 0, 0, 0};
                mma16816(d4, akh, bsh);
                mma16816(d4, akl, bsh);
                mma16816(d4, akh, bsl);
                int d0 = dm * 16 + (lane >> 2);
                int e = nn8 * 8 + (lane & 3) * 2;
                float2* m0 = (float2*)&S[FW1M + d0 * 72 + e];
                float2 v0 = *m0; v0.x -= d4[0]; v0.y -= d4[1]; *m0 = v0;
                float2* m1 = (float2*)&S[FW1M + (d0 + 8) * 72 + e];
                float2 v1 = *m1; v1.x -= d4[2]; v1.y -= d4[3]; *m1 = v1;
                uint32_t ob0 = (uint32_t)(d0 * 128 + ((nn8 ^ (d0 & 7)) << 4) +
                                          (lane & 3) * 4);
                uint32_t ob1 = (uint32_t)((d0 + 8) * 128 +
                                          ((nn8 ^ ((d0 + 8) & 7)) << 4) +
                                          (lane & 3) * 4);
                *(uint32_t*)(SMC + BW1H + ob0) = pkhi(v0.x, v0.y);
                *(uint32_t*)(SMC + BW1L + ob0) = pkhi(flo(v0.x), flo(v0.y));
                *(uint32_t*)(SMC + BW1H + ob1) = pkhi(v1.x, v1.y);
                *(uint32_t*)(SMC + BW1L + ob1) = pkhi(flo(v1.x), flo(v1.y));
            }
        }
        if (tid < ND) {
            float a = 0.f;
#pragma unroll
            for (int j = 0; j < NK; j++) a += S[FSG + j * 72 + tid];
            S[FB1 + tid] -= a;
        }
        CPA_WAIT1();
        __syncthreads();                                   // s2a

        // ---- A2: out(mb) ; X(mb+1) ; preZ(mb+2) -----------------------------
        {
            int c0 = lane, c1 = lane + 32;
            float z0 = S[FZQ(mb & 1) + w * 72 + c0] + b1o0;
            float z1 = S[FZQ(mb & 1) + w * 72 + c1] + b1o1;
            const float* cf = S + FCOEF + sl * 256 + w * 16;
#pragma unroll
            for (int j = 0; j < NK; j++) {
                float co = cf[j];
                z0 -= co * S[FSG + j * 72 + c0];
                z1 -= co * S[FSG + j * 72 + c1];
            }
            float mu = warpAllSum(z0 + z1) * (1.f / 64.f);
            float var = warpAllSum(z0 * z0 + z1 * z1) * (1.f / 64.f) - mu * mu;
            float rstd = rsqrtf(var + 1e-5f);
            uint32_t to0 = tile_off(w, c0), to1 = tile_off(w, c1);
            float q0 =
                __bfloat162float(*(__nv_bfloat16*)(SMC + bufB + to0)) +
                __bfloat162float(*(__nv_bfloat16*)(SMC + bufB + 2048 + to0));
            float q1 =
                __bfloat162float(*(__nv_bfloat16*)(SMC + bufB + to1)) +
                __bfloat162float(*(__nv_bfloat16*)(SMC + bufB + 2048 + to1));
            int s = mb * NK + w;
            float* orow = zg + (size_t)s * NHID;
            orow[c0] = q0 + (z0 - mu) * rstd * S[FGSC + c0] + S[FGBI + c0];
            orow[c1] = q1 + (z1 - mu) * rstd * S[FGSC + c1] + S[FGBI + c1];
        }
        if (mb <= 509) {
            uint32_t As = sb + (uint32_t)(BBUF + (((mb + 2) & 3) * 12288)) +
                          (mt ? 0u : 4096u);
            uint32_t Bs = sb + (uint32_t)(BBUF + (((mb + 1) & 3) * 12288)) + 4096;
            x_mma(As, Bs, rr, hf, lane, axh, axl);
            preZ[0] = preZ[1] = preZ[2] = preZ[3] = 0.f;
            kqW1_mma(As, sb, rr, hf, n8, preZ);
        }
        __syncthreads();                                   // s3
    }
}

// -------- post-norm + gelu(gate) product, writes split-bf16 G -----------------
__global__ __launch_bounds__(256) void postnorm_kernel(
    const float* __restrict__ pns, const float* __restrict__ pnb)
{
    int t = blockIdx.x;
    int tid = threadIdx.x;
    const float* zr = g_Z + (size_t)t * NHID;
    const float* gr = g_qvg + (size_t)t * KSP + 2 * NHID;
    __nv_bfloat16* orow = g_asplit + (size_t)t * KSP;

    float z0 = zr[tid], z1 = zr[tid + 256], z2 = zr[tid + 512];
    float s1 = warpAllSum(z0 + z1 + z2);
    float s2 = warpAllSum(z0 * z0 + z1 * z1 + z2 * z2);
    __shared__ float sm1[8], sm2[8];
    if ((tid & 31) == 0) { sm1[tid >> 5] = s1; sm2[tid >> 5] = s2; }
    __syncthreads();
    float T1 = 0.f, T2 = 0.f;
#pragma unroll
    for (int i = 0; i < 8; i++) { T1 += sm1[i]; T2 += sm2[i]; }
    float mu = T1 * (1.f / 768.f);
    float var = T2 * (1.f / 768.f) - mu * mu;
    float rstd = rsqrtf(var + 1e-5f);
#pragma unroll
    for (int u = 0; u < 3; u++) {
        int cidx = tid + (u << 8);
        float zz = (u == 0 ? z0 : (u == 1 ? z1 : z2));
        float zn = (zz - mu) * rstd * pns[cidx] + pnb[cidx];
        float gv = gr[cidx];
        float g3 = 0.5f * gv *
                   (1.f + tanhf(0.7978845608028654f * (gv + 0.044715f * gv * gv * gv)));
        float val = zn * g3;
        __nv_bfloat16 hi = __float2bfloat16(val);
        __nv_bfloat16 lo = __float2bfloat16(val - __bfloat162float(hi));
        orow[cidx] = hi;
        orow[NHID + cidx] = lo;
        orow[2 * NHID + cidx] = hi;
    }
}

// ------------------------------- launcher ------------------------------------
#define GEMM_DSM (1024 + 6 * STAGE_BYTES)

extern "C" void kernel_launch(void* const* d_in, const int* in_sizes, int n_in,
                              void* d_out, int out_size)
{
    const float* x   = (const float*)d_in[0];
    const float* wq  = (const float*)d_in[1];
    const float* wv  = (const float*)d_in[2];
    const float* wo  = (const float*)d_in[3];
    const float* wg  = (const float*)d_in[4];
    const float* cqw = (const float*)d_in[5];
    const float* cqb = (const float*)d_in[6];
    const float* ckw = (const float*)d_in[7];
    const float* ckb = (const float*)d_in[8];
    const float* lrw = (const float*)d_in[9];
    const float* lrb = (const float*)d_in[10];
    const float* lti = (const float*)d_in[11];
    const float* tns = (const float*)d_in[12];
    const float* tnb = (const float*)d_in[13];
    const float* pns = (const float*)d_in[14];
    const float* pnb = (const float*)d_in[15];
    const float* W1  = (const float*)d_in[16];
    const float* b1  = (const float*)d_in[17];
    float* out = (float*)d_out;

    __nv_bfloat16 *p_asplit, *p_bt1, *p_bt2;
    float *p_qvg;
    cudaGetSymbolAddress((void**)&p_asplit, g_asplit);
    cudaGetSymbolAddress((void**)&p_bt1, g_bt1);
    cudaGetSymbolAddress((void**)&p_bt2, g_bt2);
    cudaGetSymbolAddress((void**)&p_qvg, g_qvg);

    cudaFuncSetAttribute(mma_gemm, cudaFuncAttributeMaxDynamicSharedMemorySize,
                         GEMM_DSM);
    cudaFuncSetAttribute(scan_kernel, cudaFuncAttributeMaxDynamicSharedMemorySize,
                         SCAN_DSM);

    rope_init_kernel<<<1, 32>>>();
    split_x_kernel<<<NTOK, 256>>>(x);
    build_bt_t_kernel<<<dim3(24, 24), 256>>>(p_bt1, wq, 0);
    build_bt_t_kernel<<<dim3(24, 24), 256>>>(p_bt1, wv, NHID);
    build_bt_t_kernel<<<dim3(24, 24), 256>>>(p_bt1, wg, 2 * NHID);
    build_bt_t_kernel<<<dim3(24, 24), 256>>>(p_bt2, wo, 0);

    mma_gemm<<<dim3(KSP / 128, NTOK / 128), 256, GEMM_DSM>>>(p_asplit, p_bt1,
                                                             p_qvg, KSP);

    lr_kernel<<<(NTOK * 32) / 256, 256>>>(x, lrw, lrb);
    conv_rope_kernel<<<dim3(NMB, NBH), 512>>>(cqw, cqb, ckw, ckb, lti);
    scan_kernel<<<NBH, 512, SCAN_DSM>>>(lti, tns, tnb, W1, b1);
    postnorm_kernel<<<NTOK, 256>>>(pns, pnb);

    mma_gemm<<<dim3(NHID / 128, NTOK / 128), 256, GEMM_DSM>>>(p_asplit, p_bt2,
                                                              out, NHID);
}

// round 15
// speedup vs baseline: 1.1433x; 1.1433x over previous
#include <cuda_runtime.h>
#include <cuda_bf16.h>
#include <math.h>
#include <stdint.h>

// Problem constants
#define NB 4
#define NS 8192
#define NHID 768
#define NH 12
#define ND 64
#define NK 16
#define NMB (NS/NK)          // 512
#define NTOK (NB*NS)         // 32768
#define KSP 2304             // split-K (3 x 768)
#define NCH 36               // K chunks of 64
#define NBH (NB*NH)          // 48

// ---------------- scratch (device globals; no allocs allowed) ----------------
__device__ __nv_bfloat16 g_asplit[(size_t)NTOK*KSP]; // split A (x, later G)
__device__ float g_qvg[(size_t)NTOK*KSP];            // fused q|v|gate output f32
__device__ __nv_bfloat16 g_bt1[(size_t)KSP*KSP];     // Bt for qvg gemm
__device__ __nv_bfloat16 g_bt2[(size_t)NHID*KSP];    // Bt for wo gemm
// per-(bh,mb) packed record, 12288 B = 768 uint4 (all swizzled bf16 16x128B):
//   [0,2048) qh | [2048,4096) ql | [4096,6144) kh | [6144,8192) kl
//   [8192,10240) vh | [10240,12288) vl
__device__ uint4 g_rec[(size_t)NBH*NMB*768];
__device__ float g_coef[(size_t)NBH*NMB*256];        // coef' per minibatch
__device__ float g_Z[(size_t)NTOK*NHID];             // scan output [B,S,H*D]
__device__ float g_eta[NB*NH*NS];
__device__ float g_invf[32];                         // rope inv_freq table

__device__ __forceinline__ float warpAllSum(float v) {
#pragma unroll
    for (int o = 16; o; o >>= 1) v += __shfl_xor_sync(0xffffffffu, v, o);
    return v;
}

__device__ __forceinline__ uint32_t smem_u32(const void* p) {
    uint32_t a;
    asm("{ .reg .u64 t; cvta.to.shared.u64 t, %1; cvt.u32.u64 %0, t; }"
        : "=r"(a) : "l"(p));
    return a;
}

#define CPA16(sa, gp) \
    asm volatile("cp.async.cg.shared.global [%0], [%1], 16;" \
        :: "r"(sa), "l"(__cvta_generic_to_global(gp)) : "memory")
#define CPA_COMMIT() asm volatile("cp.async.commit_group;" ::: "memory")
#define CPA_WAIT2()  asm volatile("cp.async.wait_group 2;" ::: "memory")
#define CPA_WAIT1()  asm volatile("cp.async.wait_group 1;" ::: "memory")

__device__ __forceinline__ void ldsm4(uint32_t* r, uint32_t a) {
    asm volatile("ldmatrix.sync.aligned.m8n8.x4.shared.b16 {%0,%1,%2,%3}, [%4];"
        : "=r"(r[0]), "=r"(r[1]), "=r"(r[2]), "=r"(r[3]) : "r"(a));
}
__device__ __forceinline__ void ldsm4t(uint32_t* r, uint32_t a) {
    asm volatile("ldmatrix.sync.aligned.m8n8.x4.trans.shared.b16 {%0,%1,%2,%3}, [%4];"
        : "=r"(r[0]), "=r"(r[1]), "=r"(r[2]), "=r"(r[3]) : "r"(a));
}
__device__ __forceinline__ void ldsm2t(uint32_t& r0, uint32_t& r1, uint32_t a) {
    asm volatile("ldmatrix.sync.aligned.m8n8.x2.trans.shared.b16 {%0,%1}, [%2];"
        : "=r"(r0), "=r"(r1) : "r"(a));
}
__device__ __forceinline__ void mma16816(float* c, const uint32_t* a,
                                         const uint32_t* b) {
    asm volatile("mma.sync.aligned.m16n8k16.row.col.f32.bf16.bf16.f32 "
        "{%0,%1,%2,%3}, {%4,%5,%6,%7}, {%8,%9}, {%0,%1,%2,%3};"
        : "+f"(c[0]), "+f"(c[1]), "+f"(c[2]), "+f"(c[3])
        : "r"(a[0]), "r"(a[1]), "r"(a[2]), "r"(a[3]), "r"(b[0]), "r"(b[1]));
}

__device__ __forceinline__ uint32_t pkhi(float a, float b) {
    __nv_bfloat16 x = __float2bfloat16(a), y = __float2bfloat16(b);
    uint16_t ux = *(uint16_t*)&x, uy = *(uint16_t*)&y;
    return (uint32_t)ux | ((uint32_t)uy << 16);
}
__device__ __forceinline__ float flo(float v) {
    return v - __bfloat162float(__float2bfloat16(v));
}
// swizzled byte offset of bf16 element (row, col) in a 16x128B tile
__device__ __forceinline__ uint32_t tile_off(int row, int col) {
    return (uint32_t)(row * 128 + ((((col >> 3) ^ row) & 7) << 4) +
                      ((2 * col) & 15));
}

// ======================= mma.sync GEMM: C = A * Bt^T ==========================
#define STAGE_BYTES 16384
__global__ __launch_bounds__(256) void mma_gemm(
    const __nv_bfloat16* __restrict__ A, const __nv_bfloat16* __restrict__ Bt,
    float* __restrict__ C, int ldc)
{
    extern __shared__ char dsm[];
    uint32_t sbase = (smem_u32(dsm) + 1023u) & ~1023u;
    uint32_t aS = sbase;
    uint32_t bS = sbase + 3 * STAGE_BYTES;

    int tid = threadIdx.x, lane = tid & 31, w = tid >> 5;
    int m0 = blockIdx.y * 128, n0 = blockIdx.x * 128;
    int mw = (w & 1) * 64, nw = (w >> 1) * 32;

    int r0 = tid >> 3, cg = tid & 7;
    uint32_t st_off = (uint32_t)(r0 * 128 + ((cg * 16) ^ ((r0 & 7) << 4)));
    const __nv_bfloat16* ga = A  + (size_t)(m0 + r0) * KSP + cg * 8;
    const __nv_bfloat16* gb = Bt + (size_t)(n0 + r0) * KSP + cg * 8;

#pragma unroll
    for (int j = 0; j < 3; j++) {
#pragma unroll
        for (int t = 0; t < 4; t++) {
            CPA16(aS + j * STAGE_BYTES + st_off + t * 4096,
                  ga + (size_t)t * 32 * KSP + j * 64);
            CPA16(bS + j * STAGE_BYTES + st_off + t * 4096,
                  gb + (size_t)t * 32 * KSP + j * 64);
        }
        CPA_COMMIT();
    }

    uint32_t swz = (uint32_t)((lane & 7) << 4);
    uint32_t a_row_byte = (uint32_t)((mw + (lane & 15)) * 128);
    uint32_t a_khalf = (uint32_t)((lane >> 4) * 16);
    uint32_t b_row_byte = (uint32_t)((nw + (lane & 7) + ((lane >> 4) << 3)) * 128);
    uint32_t b_khalf = (uint32_t)(((lane >> 3) & 1) * 16);

    float cacc[4][4][4];
#pragma unroll
    for (int i = 0; i < 4; i++)
#pragma unroll
        for (int j = 0; j < 4; j++)
#pragma unroll
            for (int k = 0; k < 4; k++) cacc[i][j][k] = 0.f;

    for (int i = 0; i < NCH; i++) {
        int si = i % 3;
        CPA_WAIT2();
        __syncthreads();
        uint32_t aT = aS + si * STAGE_BYTES;
        uint32_t bT = bS + si * STAGE_BYTES;
#pragma unroll
        for (int ks = 0; ks < 4; ks++) {
            uint32_t afr[4][4], bfr[4][2];
#pragma unroll
            for (int am = 0; am < 4; am++) {
                uint32_t row_b = a_row_byte + am * (16 * 128);
                ldsm4(afr[am], aT + row_b + ((ks * 32 + a_khalf) ^ swz));
            }
#pragma unroll
            for (int bg = 0; bg < 2; bg++) {
                uint32_t t4[4];
                uint32_t row_b = b_row_byte + bg * (16 * 128);
                ldsm4(t4, bT + row_b + ((ks * 32 + b_khalf) ^ swz));
                bfr[bg * 2 + 0][0] = t4[0]; bfr[bg * 2 + 0][1] = t4[1];
                bfr[bg * 2 + 1][0] = t4[2]; bfr[bg * 2 + 1][1] = t4[3];
            }
#pragma unroll
            for (int am = 0; am < 4; am++)
#pragma unroll
                for (int bn = 0; bn < 4; bn++)
                    mma16816(cacc[am][bn], afr[am], bfr[bn]);
        }
        __syncthreads();
        int jn = i + 3;
        if (jn < NCH) {
#pragma unroll
            for (int t = 0; t < 4; t++) {
                CPA16(aS + si * STAGE_BYTES + st_off + t * 4096,
                      ga + (size_t)t * 32 * KSP + jn * 64);
                CPA16(bS + si * STAGE_BYTES + st_off + t * 4096,
                      gb + (size_t)t * 32 * KSP + jn * 64);
            }
        }
        CPA_COMMIT();
    }

    int erow = lane >> 2, ecol = (lane & 3) * 2;
#pragma unroll
    for (int am = 0; am < 4; am++) {
#pragma unroll
        for (int bn = 0; bn < 4; bn++) {
            int r = m0 + mw + am * 16 + erow;
            int c = n0 + nw + bn * 8 + ecol;
            *(float2*)&C[(size_t)r * ldc + c] =
                make_float2(cacc[am][bn][0], cacc[am][bn][1]);
            *(float2*)&C[(size_t)(r + 8) * ldc + c] =
                make_float2(cacc[am][bn][2], cacc[am][bn][3]);
        }
    }
}

// ---------------- rope inv_freq table (double-rounded, once) ------------------
__global__ void rope_init_kernel()
{
    int p = threadIdx.x;
    double ex = (double)(2 * p) / 64.0;
    g_invf[p] = (float)exp(-ex * 9.210340371976184);   // 10000^-ex
}

// ---------------- conversion: x -> split bf16 [Ah|Al|Ah] ----------------------
__global__ __launch_bounds__(256) void split_x_kernel(const float* __restrict__ x)
{
    size_t t = blockIdx.x;
    __nv_bfloat16* dst = g_asplit + t * KSP;
    const float* src = x + t * NHID;
#pragma unroll
    for (int u = 0; u < 3; u++) {
        int cidx = threadIdx.x + (u << 8);
        float v = src[cidx];
        __nv_bfloat16 hi = __float2bfloat16(v);
        __nv_bfloat16 lo = __float2bfloat16(v - __bfloat162float(hi));
        dst[cidx] = hi;
        dst[NHID + cidx] = lo;
        dst[2 * NHID + cidx] = hi;
    }
}

// -------- build transposed split weights via smem transpose (coalesced) -------
__global__ __launch_bounds__(256) void build_bt_t_kernel(
    __nv_bfloat16* __restrict__ dst, const float* __restrict__ w, int np_base)
{
    __shared__ float t[32][33];
    int n0 = blockIdx.x * 32, k0 = blockIdx.y * 32;
    int tx = threadIdx.x & 31, ty = threadIdx.x >> 5;   // 32 x 8
#pragma unroll
    for (int i = ty; i < 32; i += 8)
        t[i][tx] = w[(size_t)(k0 + i) * NHID + n0 + tx];
    __syncthreads();
#pragma unroll
    for (int r = ty; r < 32; r += 8) {
        float v = t[tx][r];
        __nv_bfloat16 hi = __float2bfloat16(v);
        __nv_bfloat16 lo = __float2bfloat16(v - __bfloat162float(hi));
        __nv_bfloat16* drow = dst + (size_t)(np_base + n0 + r) * KSP + k0 + tx;
        drow[0] = hi;
        drow[NHID] = hi;
        drow[2 * NHID] = lo;
    }
}

// ---------------- ttt_lr_eta = sigmoid(x . lr_w[h] + lr_b[h]) / D -------------
__global__ __launch_bounds__(256) void lr_kernel(
    const float* __restrict__ x, const float* __restrict__ lrw,
    const float* __restrict__ lrb)
{
    int gw = (blockIdx.x * blockDim.x + threadIdx.x) >> 5;
    int lane = threadIdx.x & 31;
    const float* xr = x + (size_t)gw * NHID;
    float xv[24];
#pragma unroll
    for (int u = 0; u < 24; u++) xv[u] = xr[lane + (u << 5)];
    int b = gw >> 13;
    int s = gw & (NS - 1);
    for (int h = 0; h < NH; h++) {
        const float* wr = lrw + h * NHID;
        float sum = 0.f;
#pragma unroll
        for (int u = 0; u < 24; u++) sum += xv[u] * wr[lane + (u << 5)];
        sum = warpAllSum(sum);
        if (lane == 0) {
            float zv = sum + lrb[h];
            g_eta[((size_t)b * NH + h) * NS + s] =
                (1.0f / (1.0f + expf(-zv))) * (1.0f / (float)ND);
        }
    }
}

// ------ causal dwconv + RoPE -> slim record (bf16 hi/lo tiles) + coef' --------
__global__ __launch_bounds__(512) void conv_rope_kernel(
    const float* __restrict__ cqw, const float* __restrict__ cqb,
    const float* __restrict__ ckw, const float* __restrict__ ckb,
    const float* __restrict__ lti)
{
    __shared__ float qs[16 * 68], ks[16 * 68], tkl[16];
    int mb = blockIdx.x, bh = blockIdx.y;
    int b = bh / NH, h = bh % NH;
    int tid = threadIdx.x;
    int w = tid >> 5, p = tid & 31;
    int s = mb * NK + w;
    int c0 = h * ND + 2 * p;

    float qe = cqb[c0], qo = cqb[c0 + 1];
    float ke = ckb[c0], ko = ckb[c0 + 1];
    const float* xb = g_qvg + ((size_t)b * NS) * KSP + c0;
#pragma unroll
    for (int kk = 0; kk < 4; kk++) {
        int ss = s + kk - 4;
        if (ss >= 0) {
            float2 xv2 = *(const float2*)(xb + (size_t)ss * KSP);
            float2 w1 = *(const float2*)(cqw + kk * NHID + c0);
            float2 w2 = *(const float2*)(ckw + kk * NHID + c0);
            qe += w1.x * xv2.x; qo += w1.y * xv2.y;
            ke += w2.x * xv2.x; ko += w2.y * xv2.y;
        }
    }
    float invf = g_invf[p];
    float ang = (float)s * invf;
    float sn, cn;
    sincosf(ang, &sn, &cn);

    float2 qO = make_float2(qe * cn - qo * sn, qe * sn + qo * cn);
    float2 kO = make_float2(ke * cn - ko * sn, ke * sn + ko * cn);
    float2 vv = *(const float2*)(g_qvg + ((size_t)b * NS + s) * KSP + NHID + c0);

    char* rec = (char*)g_rec + ((size_t)bh * NMB + mb) * 12288;
    uint32_t so = (uint32_t)(w * 128 + ((((p >> 2) ^ w) & 7) << 4) + 4 * (p & 3));

    *(uint32_t*)(rec + 0     + so) = pkhi(qO.x, qO.y);
    *(uint32_t*)(rec + 2048  + so) = pkhi(flo(qO.x), flo(qO.y));
    *(uint32_t*)(rec + 4096  + so) = pkhi(kO.x, kO.y);
    *(uint32_t*)(rec + 6144  + so) = pkhi(flo(kO.x), flo(kO.y));
    *(uint32_t*)(rec + 8192  + so) = pkhi(vv.x, vv.y);
    *(uint32_t*)(rec + 10240 + so) = pkhi(flo(vv.x), flo(vv.y));

    qs[w * 68 + 2 * p] = qO.x; qs[w * 68 + 2 * p + 1] = qO.y;
    ks[w * 68 + 2 * p] = kO.x; ks[w * 68 + 2 * p + 1] = kO.y;
    if (tid < 16) tkl[tid] = fmaxf(1.0f / (float)(tid + 1) + lti[tid], 0.0f);
    __syncthreads();

    if (tid < 256) {
        int i = tid >> 4, j = tid & 15;
        float a = 0.f;
#pragma unroll 8
        for (int d = 0; d < ND; d++) a += qs[i * 68 + d] * ks[j * 68 + d];
        float invlc = 1.0f / tkl[15];
        g_coef[((size_t)bh * NMB + mb) * 256 + tid] =
            (j <= i) ? tkl[i] * (a + 1.0f) * invlc : 0.0f;
    }
}

// ---------------- the sequential TTT scan: 48 blocks, 512 threads -------------
// fp32 scratch rows use stride 72 (conflict-free float2 phases)
#define FW1M  0        // 64*72 fp32 master W1
#define FZK   4608
#define FZQ   5760
#define FSG   6912
#define FB1   8064
#define FGSC  8128
#define FGBI  8192
#define FETA  8256     // 2*16  (ends 8288)
#define FCOEF 8288     // 2*256 (ends 8800)
#define FLC   8800
// byte offsets
#define BW1H  35216    // 64x128B swizzled bf16
#define BW1L  43408
#define BSGH  51600    // 16x128B
#define BSGL  53648
#define BBUF0 55696    // 12288: qh ql kh kl vh vl tiles
#define BBUF1 67984
#define SCAN_DSM 80288

__global__ __launch_bounds__(512) void scan_kernel(
    const float* __restrict__ lti, const float* __restrict__ tns,
    const float* __restrict__ tnb, const float* __restrict__ W1g,
    const float* __restrict__ b1g)
{
    extern __shared__ char SMC[];
    float* S = (float*)SMC;
    uint32_t sb = smem_u32(SMC);

    int bh = blockIdx.x;
    int b = bh / NH, h = bh % NH;
    int tid = threadIdx.x;
    int w = tid >> 5, lane = tid & 31;

    for (int i = tid; i < ND * ND; i += 512) {
        int d = i >> 6, e = i & 63;
        float wv = W1g[h * ND * ND + i];
        S[FW1M + d * 72 + e] = wv;
        uint32_t off = tile_off(d, e);
        *(__nv_bfloat16*)(SMC + BW1H + off) = __float2bfloat16(wv);
        *(__nv_bfloat16*)(SMC + BW1L + off) = __float2bfloat16(flo(wv));
    }
    if (tid < ND) {
        S[FB1 + tid]  = b1g[h * ND + tid];
        S[FGSC + tid] = tns[h * ND + tid];
        S[FGBI + tid] = tnb[h * ND + tid];
    }
    if (tid == 0) S[FLC] = fmaxf(1.0f / 16.0f + lti[15], 0.0f);

    const uint4* recb = g_rec + (size_t)bh * NMB * 768;
    const float* eg = g_eta + (size_t)bh * NS;
    const float* cfb = g_coef + (size_t)bh * NMB * 256;
    float* zg = g_Z + (size_t)b * NS * NHID + h * ND;

    // prefetch mb 0 -> buffer 0 (768 tile chunks + 64 coef + 4 eta = 836)
    {
        for (int idx = tid; idx < 836; idx += 512) {
            if (idx < 768) {
                CPA16(sb + BBUF0 + idx * 16, recb + idx);
            } else if (idx < 832) {
                int c = idx - 768;
                CPA16(sb + FCOEF * 4 + c * 16, cfb + c * 4);
            } else {
                int c = idx - 832;
                CPA16(sb + FETA * 4 + c * 16, eg + c * 4);
            }
        }
        CPA_COMMIT();
    }

    for (int mb = 0; mb < NMB; mb++) {
        int buf = mb & 1;
        uint32_t bufB = buf ? BBUF1 : BBUF0;
        if (mb + 1 < NMB) {
            int nb = buf ^ 1;
            uint32_t nbB = nb ? BBUF1 : BBUF0;
            const uint4* rec = recb + (size_t)(mb + 1) * 768;
            for (int idx = tid; idx < 836; idx += 512) {
                if (idx < 768) {
                    CPA16(sb + nbB + idx * 16, rec + idx);
                } else if (idx < 832) {
                    int c = idx - 768;
                    CPA16(sb + (FCOEF + nb * 256) * 4 + c * 16,
                          cfb + (size_t)(mb + 1) * 256 + c * 4);
                } else {
                    int c = idx - 832;
                    CPA16(sb + (FETA + nb * 16) * 4 + c * 16,
                          eg + (size_t)(mb + 1) * 16 + c * 4);
                }
            }
        }
        CPA_COMMIT();
        CPA_WAIT1();
        __syncthreads();                                   // sync 1

        // ---- P1: Z1k / Z1q via mma (split-bf16, two independent chains) -----
        {
            int mt = w & 1, n8 = w >> 1;
            uint32_t Ab = sb + bufB + (mt ? 0u : 4096u);   // mt0=k, mt1=q
            int rr = lane & 15, hf = lane >> 4;
            uint32_t ah[4][4], al[4][4];
#pragma unroll
            for (int c = 0; c < 4; c++) {
                uint32_t ad = Ab + rr * 128 +
                              ((((c << 1) | hf) ^ (rr & 7)) << 4);
                ldsm4(ah[c], ad);
                ldsm4(al[c], ad + 2048);
            }
            uint32_t bhf[4][2], blf[4][2];
#pragma unroll
            for (int c = 0; c < 4; c++) {
                int rb = (c << 4) + rr;
                uint32_t woff = (uint32_t)(rb * 128 + ((n8 ^ (rb & 7)) << 4));
                ldsm2t(bhf[c][0], bhf[c][1], sb + BW1H + woff);
                ldsm2t(blf[c][0], blf[c][1], sb + BW1L + woff);
            }
            float accA[4] = {0, 0, 0, 0}, accB[4] = {0, 0, 0, 0};
#pragma unroll
            for (int c = 0; c < 2; c++) {
                mma16816(accA, ah[c], bhf[c]);
                mma16816(accA, al[c], bhf[c]);
                mma16816(accA, ah[c], blf[c]);
            }
#pragma unroll
            for (int c = 2; c < 4; c++) {
                mma16816(accB, ah[c], bhf[c]);
                mma16816(accB, al[c], bhf[c]);
                mma16816(accB, ah[c], blf[c]);
            }

            int e = n8 * 8 + (lane & 3) * 2, r0 = lane >> 2;
            float bb0 = S[FB1 + e], bb1 = S[FB1 + e + 1];
            float* Z = S + (mt ? FZQ : FZK);
            *(float2*)&Z[r0 * 72 + e] =
                make_float2(accA[0] + accB[0] + bb0, accA[1] + accB[1] + bb1);
            *(float2*)&Z[(r0 + 8) * 72 + e] =
                make_float2(accA[2] + accB[2] + bb0, accA[3] + accB[3] + bb1);
        }
        __syncthreads();                                   // sync 2

        // ---- P2 (row w): LN-L2 bwd -> SG (f32 + split bf16) -----------------
        {
            int c0 = lane, c1 = lane + 32;
            float z0 = S[FZK + w * 72 + c0], z1 = S[FZK + w * 72 + c1];
            float mu = warpAllSum(z0 + z1) * (1.f / 64.f);
            float var = warpAllSum(z0 * z0 + z1 * z1) * (1.f / 64.f) - mu * mu;
            float rstd = rsqrtf(var + 1e-5f);
            float xh0 = (z0 - mu) * rstd, xh1 = (z1 - mu) * rstd;
            float g0 = S[FGSC + c0], g1 = S[FGSC + c1];
            uint32_t to0 = tile_off(w, c0), to1 = tile_off(w, c1);
            float t0 =
                (__bfloat162float(*(__nv_bfloat16*)(SMC + bufB + 8192 + to0)) +
                 __bfloat162float(*(__nv_bfloat16*)(SMC + bufB + 10240 + to0))) -
                (__bfloat162float(*(__nv_bfloat16*)(SMC + bufB + 4096 + to0)) +
                 __bfloat162float(*(__nv_bfloat16*)(SMC + bufB + 6144 + to0)));
            float t1 =
                (__bfloat162float(*(__nv_bfloat16*)(SMC + bufB + 8192 + to1)) +
                 __bfloat162float(*(__nv_bfloat16*)(SMC + bufB + 10240 + to1))) -
                (__bfloat162float(*(__nv_bfloat16*)(SMC + bufB + 4096 + to1)) +
                 __bfloat162float(*(__nv_bfloat16*)(SMC + bufB + 6144 + to1)));
            float gx0 = (xh0 * g0 + S[FGBI + c0] - t0) * g0;
            float gx1 = (xh1 * g1 + S[FGBI + c1] - t1) * g1;
            float m1 = warpAllSum(gx0 + gx1) * (1.f / 64.f);
            float m2 = warpAllSum(gx0 * xh0 + gx1 * xh1) * (1.f / 64.f);
            float sgs = S[FLC] * S[FETA + buf * 16 + w];
            float sg0 = sgs * (gx0 - m1 - xh0 * m2) * rstd;
            float sg1 = sgs * (gx1 - m1 - xh1 * m2) * rstd;
            S[FSG + w * 72 + c0] = sg0;
            S[FSG + w * 72 + c1] = sg1;
            *(__nv_bfloat16*)(SMC + BSGH + to0) = __float2bfloat16(sg0);
            *(__nv_bfloat16*)(SMC + BSGH + to1) = __float2bfloat16(sg1);
            *(__nv_bfloat16*)(SMC + BSGL + to0) = __float2bfloat16(flo(sg0));
            *(__nv_bfloat16*)(SMC + BSGL + to1) = __float2bfloat16(flo(sg1));
        }
        __syncthreads();                                   // sync 3

        // ---- P3 (warp-specialized): warps 0-7 out rows; warps 8-15 W1+b1 ----
        if (w < 8) {
            int c0 = lane, c1 = lane + 32;
#pragma unroll
            for (int rx = 0; rx < 2; rx++) {
                int r = 2 * w + rx;
                float z0 = S[FZQ + r * 72 + c0], z1 = S[FZQ + r * 72 + c1];
                const float* cf = S + FCOEF + buf * 256 + r * 16;
#pragma unroll
                for (int j = 0; j < NK; j++) {
                    float co = cf[j];
                    z0 -= co * S[FSG + j * 72 + c0];
                    z1 -= co * S[FSG + j * 72 + c1];
                }
                float mu = warpAllSum(z0 + z1) * (1.f / 64.f);
                float var = warpAllSum(z0 * z0 + z1 * z1) * (1.f / 64.f) -
                            mu * mu;
                float rstd = rsqrtf(var + 1e-5f);
                uint32_t to0 = tile_off(r, c0), to1 = tile_off(r, c1);
                float q0 =
                    __bfloat162float(*(__nv_bfloat16*)(SMC + bufB + to0)) +
                    __bfloat162float(*(__nv_bfloat16*)(SMC + bufB + 2048 + to0));
                float q1 =
                    __bfloat162float(*(__nv_bfloat16*)(SMC + bufB + to1)) +
                    __bfloat162float(*(__nv_bfloat16*)(SMC + bufB + 2048 + to1));
                int s = mb * NK + r;
                float* orow = zg + (size_t)s * NHID;
                orow[c0] = q0 + (z0 - mu) * rstd * S[FGSC + c0] + S[FGBI + c0];
                orow[c1] = q1 + (z1 - mu) * rstd * S[FGSC + c1] + S[FGBI + c1];
            }
        } else {
            int w2 = w - 8;
            int dm = w2 & 3, np = w2 >> 2;    // np in {0,1}
            int rr = lane & 15, hf = lane >> 4;
            uint32_t kb = sb + bufB + 4096;   // kh tile
            uint32_t adr = kb + rr * 128 +
                           ((((dm << 1) | hf) ^ (rr & 7)) << 4);
            uint32_t tmp[4], akh[4], akl[4];
            ldsm4t(tmp, adr);
            akh[0] = tmp[0]; akh[1] = tmp[2]; akh[2] = tmp[1]; akh[3] = tmp[3];
            ldsm4t(tmp, adr + 2048);
            akl[0] = tmp[0]; akl[1] = tmp[2]; akl[2] = tmp[1]; akl[3] = tmp[3];
#pragma unroll
            for (int sdx = 0; sdx < 4; sdx++) {
                int n8 = np * 4 + sdx;
                uint32_t so = (uint32_t)(rr * 128 + ((n8 ^ (rr & 7)) << 4));
                uint32_t bsh[2], bsl[2];
                ldsm2t(bsh[0], bsh[1], sb + BSGH + so);
                ldsm2t(bsl[0], bsl[1], sb + BSGL + so);
                float d4[4] = {0, 0, 0, 0};
                mma16816(d4, akh, bsh);
                mma16816(d4, akl, bsh);
                mma16816(d4, akh, bsl);
                int d0 = dm * 16 + (lane >> 2);
                int e = n8 * 8 + (lane & 3) * 2;
                float2* m0 = (float2*)&S[FW1M + d0 * 72 + e];
                float2 v0 = *m0; v0.x -= d4[0]; v0.y -= d4[1]; *m0 = v0;
                float2* m1 = (float2*)&S[FW1M + (d0 + 8) * 72 + e];
                float2 v1 = *m1; v1.x -= d4[2]; v1.y -= d4[3]; *m1 = v1;
                uint32_t ob0 = (uint32_t)(d0 * 128 + ((n8 ^ (d0 & 7)) << 4) +
                                          (lane & 3) * 4);
                uint32_t ob1 = (uint32_t)((d0 + 8) * 128 +
                                          ((n8 ^ ((d0 + 8) & 7)) << 4) +
                                          (lane & 3) * 4);
                *(uint32_t*)(SMC + BW1H + ob0) = pkhi(v0.x, v0.y);
                *(uint32_t*)(SMC + BW1L + ob0) = pkhi(flo(v0.x), flo(v0.y));
                *(uint32_t*)(SMC + BW1H + ob1) = pkhi(v1.x, v1.y);
                *(uint32_t*)(SMC + BW1L + ob1) = pkhi(flo(v1.x), flo(v1.y));
            }
            if (w2 < 2) {                      // b1 -= sum_j SG[j]
                int idx = w2 * 32 + lane;
                float a = 0.f;
#pragma unroll
                for (int j = 0; j < NK; j++) a += S[FSG + j * 72 + idx];
                S[FB1 + idx] -= a;
            }
        }
        __syncthreads();                                   // sync 4
    }
}

// -------- post-norm + gelu(gate) product, writes split-bf16 G -----------------
__global__ __launch_bounds__(256) void postnorm_kernel(
    const float* __restrict__ pns, const float* __restrict__ pnb)
{
    int t = blockIdx.x;
    int tid = threadIdx.x;
    const float* zr = g_Z + (size_t)t * NHID;
    const float* gr = g_qvg + (size_t)t * KSP + 2 * NHID;
    __nv_bfloat16* orow = g_asplit + (size_t)t * KSP;

    float z0 = zr[tid], z1 = zr[tid + 256], z2 = zr[tid + 512];
    float s1 = warpAllSum(z0 + z1 + z2);
    float s2 = warpAllSum(z0 * z0 + z1 * z1 + z2 * z2);
    __shared__ float sm1[8], sm2[8];
    if ((tid & 31) == 0) { sm1[tid >> 5] = s1; sm2[tid >> 5] = s2; }
    __syncthreads();
    float T1 = 0.f, T2 = 0.f;
#pragma unroll
    for (int i = 0; i < 8; i++) { T1 += sm1[i]; T2 += sm2[i]; }
    float mu = T1 * (1.f / 768.f);
    float var = T2 * (1.f / 768.f) - mu * mu;
    float rstd = rsqrtf(var + 1e-5f);
#pragma unroll
    for (int u = 0; u < 3; u++) {
        int cidx = tid + (u << 8);
        float zz = (u == 0 ? z0 : (u == 1 ? z1 : z2));
        float zn = (zz - mu) * rstd * pns[cidx] + pnb[cidx];
        float gv = gr[cidx];
        float g3 = 0.5f * gv *
                   (1.f + tanhf(0.7978845608028654f * (gv + 0.044715f * gv * gv * gv)));
        float val = zn * g3;
        __nv_bfloat16 hi = __float2bfloat16(val);
        __nv_bfloat16 lo = __float2bfloat16(val - __bfloat162float(hi));
        orow[cidx] = hi;
        orow[NHID + cidx] = lo;
        orow[2 * NHID + cidx] = hi;
    }
}

// ------------------------------- launcher ------------------------------------
#define GEMM_DSM (1024 + 6 * STAGE_BYTES)

extern "C" void kernel_launch(void* const* d_in, const int* in_sizes, int n_in,
                              void* d_out, int out_size)
{
    const float* x   = (const float*)d_in[0];
    const float* wq  = (const float*)d_in[1];
    const float* wv  = (const float*)d_in[2];
    const float* wo  = (const float*)d_in[3];
    const float* wg  = (const float*)d_in[4];
    const float* cqw = (const float*)d_in[5];
    const float* cqb = (const float*)d_in[6];
    const float* ckw = (const float*)d_in[7];
    const float* ckb = (const float*)d_in[8];
    const float* lrw = (const float*)d_in[9];
    const float* lrb = (const float*)d_in[10];
    const float* lti = (const float*)d_in[11];
    const float* tns = (const float*)d_in[12];
    const float* tnb = (const float*)d_in[13];
    const float* pns = (const float*)d_in[14];
    const float* pnb = (const float*)d_in[15];
    const float* W1  = (const float*)d_in[16];
    const float* b1  = (const float*)d_in[17];
    float* out = (float*)d_out;

    __nv_bfloat16 *p_asplit, *p_bt1, *p_bt2;
    float *p_qvg;
    cudaGetSymbolAddress((void**)&p_asplit, g_asplit);
    cudaGetSymbolAddress((void**)&p_bt1, g_bt1);
    cudaGetSymbolAddress((void**)&p_bt2, g_bt2);
    cudaGetSymbolAddress((void**)&p_qvg, g_qvg);

    cudaFuncSetAttribute(mma_gemm, cudaFuncAttributeMaxDynamicSharedMemorySize,
                         GEMM_DSM);
    cudaFuncSetAttribute(scan_kernel, cudaFuncAttributeMaxDynamicSharedMemorySize,
                         SCAN_DSM);

    rope_init_kernel<<<1, 32>>>();
    split_x_kernel<<<NTOK, 256>>>(x);
    build_bt_t_kernel<<<dim3(24, 24), 256>>>(p_bt1, wq, 0);
    build_bt_t_kernel<<<dim3(24, 24), 256>>>(p_bt1, wv, NHID);
    build_bt_t_kernel<<<dim3(24, 24), 256>>>(p_bt1, wg, 2 * NHID);
    build_bt_t_kernel<<<dim3(24, 24), 256>>>(p_bt2, wo, 0);

    mma_gemm<<<dim3(KSP / 128, NTOK / 128), 256, GEMM_DSM>>>(p_asplit, p_bt1,
                                                             p_qvg, KSP);

    lr_kernel<<<(NTOK * 32) / 256, 256>>>(x, lrw, lrb);
    conv_rope_kernel<<<dim3(NMB, NBH), 512>>>(cqw, cqb, ckw, ckb, lti);
    scan_kernel<<<NBH, 512, SCAN_DSM>>>(lti, tns, tnb, W1, b1);
    postnorm_kernel<<<NTOK, 256>>>(pns, pnb);

    mma_gemm<<<dim3(NHID / 128, NTOK / 128), 256, GEMM_DSM>>>(p_asplit, p_bt2,
                                                              out, NHID);
}